// round 16
// baseline (speedup 1.0000x reference)
#include <cuda_runtime.h>
#include <cuda_bf16.h>
#include <cuda_fp16.h>
#include <cmath>
#include <cstdint>

#define NMAX 50000
#define EMAX 800000
#define HC   256
#define NH   8
#define NEG  0.2f

// ---------------- scratch (static device globals; no allocation) ----------------
__device__ __half g_hlinh1[NMAX * HC];
__device__ __half g_hlinh2[NMAX * HC];
__device__ float g_h1  [NMAX * HC];
__device__ __half g_h16 [NMAX * HC];
__device__ float g_as1 [NMAX * NH];
__device__ float g_ad1 [NMAX * NH];
__device__ float g_as2 [NMAX * NH];
__device__ float g_ad2 [NMAX * NH];
__device__ int   g_deg [NMAX];
__device__ int   g_rowptr[NMAX];
__device__ int   g_rowend[NMAX];
__device__ int   g_cursor[NMAX];
__device__ int   g_adj [EMAX + NMAX];
__device__ int   g_eid [EMAX + NMAX];
__device__ int   g_counter;
__device__ __nv_bfloat16 g_wthi1[HC * 128];
__device__ __nv_bfloat16 g_wtlo1[HC * 128];
__device__ __nv_bfloat16 g_wthi2[HC * HC];
__device__ __nv_bfloat16 g_wtlo2[HC * HC];

__device__ __forceinline__ float leaky(float v) { return v > 0.0f ? v : NEG * v; }

__device__ __forceinline__ void cp_async16(void* dst, const void* src) {
    uint32_t d = (uint32_t)__cvta_generic_to_shared(dst);
    asm volatile("cp.async.cg.shared.global [%0], [%1], 16;" :: "r"(d), "l"(src));
}

// ---------------- CSR build (scan-free, merged kernels) ----------------
__global__ __launch_bounds__(512) void count_kernel(
    const int* __restrict__ ei, int* __restrict__ deg, int E)
{
    int e = blockIdx.x * blockDim.x + threadIdx.x;
    if (e < E) atomicAdd(&deg[__ldg(ei + E + e)], 1);
}

// alloc + self-place fused; deg holds real-edge counts (0-init), +1 self loop here
__global__ __launch_bounds__(512) void alloc_kernel(
    const int* __restrict__ deg, int* __restrict__ rowptr, int* __restrict__ rowend,
    int* __restrict__ counter, int* __restrict__ adj, int* __restrict__ cursor, int N)
{
    int d = blockIdx.x * blockDim.x + threadIdx.x;
    int lane = threadIdx.x & 31;
    int v = (d < N) ? (deg[d] + 1) : 0;
    int pre = v;
#pragma unroll
    for (int o = 1; o < 32; o <<= 1) {
        int t = __shfl_up_sync(0xffffffffu, pre, o);
        if (lane >= o) pre += t;
    }
    int wsum = __shfl_sync(0xffffffffu, pre, 31);
    int base = 0;
    if (lane == 31) base = atomicAdd(counter, wsum);
    base = __shfl_sync(0xffffffffu, base, 31);
    if (d < N) {
        int start = base + pre - v;
        rowptr[d] = start;
        rowend[d] = start + v;
        adj[start] = d;           // self loop first
        cursor[d] = start + 1;
    }
}

__global__ __launch_bounds__(512) void edge_place_kernel(
    const int* __restrict__ ei,
    int* __restrict__ cursor, int* __restrict__ adj,
    int* __restrict__ eid, int E)
{
    int e = blockIdx.x * blockDim.x + threadIdx.x;
    if (e < E) {
        int dst = __ldg(ei + E + e);
        int p = atomicAdd(&cursor[dst], 1);
        adj[p] = __ldg(ei + e);
        eid[p] = e;
    }
}

// ---------------- weight transpose + bf16 hi/lo split ----------------
__global__ void wt_convert(const float* __restrict__ W,
                           __nv_bfloat16* __restrict__ hi,
                           __nv_bfloat16* __restrict__ lo, int K)
{
    int idx = blockIdx.x * blockDim.x + threadIdx.x;
    if (idx >= K * HC) return;
    int k = idx >> 8, n = idx & 255;
    float v = W[idx];
    __nv_bfloat16 h = __float2bfloat16(v);
    hi[(size_t)n * K + k] = h;
    lo[(size_t)n * K + k] = __float2bfloat16(v - __bfloat162float(h));
}

// ---------------- pipelined mma.sync bf16x2-split GEMM (BK=32, 2 CTAs/SM) -------
#define SROW 40
#define OAH 0
#define OAL 10240
#define OBH 20480
#define OBL 30720
#define STAGE 40960
#define GEMM_SMEM (2 * STAGE)

#define MMA_BF16(d, a, b)                                                     \
    asm volatile(                                                             \
        "mma.sync.aligned.m16n8k16.row.col.f32.bf16.bf16.f32 "                \
        "{%0,%1,%2,%3}, {%4,%5,%6,%7}, {%8,%9}, {%0,%1,%2,%3};"               \
        : "+f"(d[0]), "+f"(d[1]), "+f"(d[2]), "+f"(d[3])                      \
        : "r"(a[0]), "r"(a[1]), "r"(a[2]), "r"(a[3]), "r"(b[0]), "r"(b[1]))

__device__ __forceinline__ void load_a_regs(
    float4* av, const float* A, int M, int K, int m0, int kc, int tid)
{
#pragma unroll
    for (int it = 0; it < 4; ++it) {
        int p = tid + it * 256;
        int row = p >> 3, c4 = p & 7;
        av[it] = (m0 + row < M)
            ? *(const float4*)(A + (size_t)(m0 + row) * K + kc + c4 * 4)
            : make_float4(0.f, 0.f, 0.f, 0.f);
    }
}

__device__ __forceinline__ void sts_a(char* sb, const float4* av, int tid)
{
    __nv_bfloat16* sAh = (__nv_bfloat16*)(sb + OAH);
    __nv_bfloat16* sAl = (__nv_bfloat16*)(sb + OAL);
#pragma unroll
    for (int it = 0; it < 4; ++it) {
        int p = tid + it * 256;
        int row = p >> 3, c4 = p & 7;
        float4 v = av[it];
        __nv_bfloat16 h0 = __float2bfloat16(v.x), h1 = __float2bfloat16(v.y);
        __nv_bfloat16 h2 = __float2bfloat16(v.z), h3 = __float2bfloat16(v.w);
        __nv_bfloat16 l0 = __float2bfloat16(v.x - __bfloat162float(h0));
        __nv_bfloat16 l1 = __float2bfloat16(v.y - __bfloat162float(h1));
        __nv_bfloat16 l2 = __float2bfloat16(v.z - __bfloat162float(h2));
        __nv_bfloat16 l3 = __float2bfloat16(v.w - __bfloat162float(h3));
        int o = row * SROW + c4 * 4;
        *(__nv_bfloat162*)(sAh + o)     = __halves2bfloat162(h0, h1);
        *(__nv_bfloat162*)(sAh + o + 2) = __halves2bfloat162(h2, h3);
        *(__nv_bfloat162*)(sAl + o)     = __halves2bfloat162(l0, l1);
        *(__nv_bfloat162*)(sAl + o + 2) = __halves2bfloat162(l2, l3);
    }
}

__device__ __forceinline__ void cp_b(
    char* sb, const __nv_bfloat16* Bh, const __nv_bfloat16* Bl,
    int K, int n0, int kc, int tid)
{
#pragma unroll
    for (int it = 0; it < 2; ++it) {
        int p = tid + it * 256;
        int row = p >> 2, q = p & 3;
        cp_async16(sb + OBH + row * (SROW * 2) + q * 16,
                   (const char*)(Bh + (size_t)(n0 + row) * K + kc) + q * 16);
        cp_async16(sb + OBL + row * (SROW * 2) + q * 16,
                   (const char*)(Bl + (size_t)(n0 + row) * K + kc) + q * 16);
    }
    asm volatile("cp.async.commit_group;" ::: "memory");
}

__global__ __launch_bounds__(256, 2) void gemm_mma(
    const float* __restrict__ A, const __nv_bfloat16* __restrict__ Bh,
    const __nv_bfloat16* __restrict__ Bl, __half* __restrict__ Ch,
    int M, int K,
    const float* __restrict__ att_s, const float* __restrict__ att_d,
    float* __restrict__ pas, float* __restrict__ pad_)
{
    extern __shared__ char smem[];
    int tid = threadIdx.x, wid = tid >> 5, lane = tid & 31;
    int wm = wid & 3, wn = wid >> 2;
    int m0 = blockIdx.y * 128;
    int n0 = blockIdx.x * 128;

    float acc[2][8][4];
#pragma unroll
    for (int mi = 0; mi < 2; ++mi)
#pragma unroll
        for (int ni = 0; ni < 8; ++ni)
#pragma unroll
            for (int q = 0; q < 4; ++q) acc[mi][ni][q] = 0.0f;

    int r = lane >> 2, c2 = lane & 3;
    int nch = K >> 5;

    float4 av[4];
    load_a_regs(av, A, M, K, m0, 0, tid);
    cp_b(smem, Bh, Bl, K, n0, 0, tid);
    sts_a(smem, av, tid);
    asm volatile("cp.async.wait_group 0;" ::: "memory");
    __syncthreads();

    for (int c = 0; c < nch; ++c) {
        char* sb = smem + (c & 1) * STAGE;
        char* sn = smem + ((c + 1) & 1) * STAGE;
        bool pf = (c + 1) < nch;
        if (pf) {
            load_a_regs(av, A, M, K, m0, (c + 1) * 32, tid);
            cp_b(sn, Bh, Bl, K, n0, (c + 1) * 32, tid);
        }

        __nv_bfloat16* sAh = (__nv_bfloat16*)(sb + OAH);
        __nv_bfloat16* sAl = (__nv_bfloat16*)(sb + OAL);
        __nv_bfloat16* sBh = (__nv_bfloat16*)(sb + OBH);
        __nv_bfloat16* sBl = (__nv_bfloat16*)(sb + OBL);

#pragma unroll
        for (int k16 = 0; k16 < 2; ++k16) {
            int kb = k16 * 16;
            uint32_t ah[2][4], al[2][4];
#pragma unroll
            for (int mi = 0; mi < 2; ++mi) {
                int br = wm * 32 + mi * 16 + r;
                int kcol = kb + c2 * 2;
                ah[mi][0] = *(const uint32_t*)(sAh + br * SROW + kcol);
                ah[mi][1] = *(const uint32_t*)(sAh + (br + 8) * SROW + kcol);
                ah[mi][2] = *(const uint32_t*)(sAh + br * SROW + kcol + 8);
                ah[mi][3] = *(const uint32_t*)(sAh + (br + 8) * SROW + kcol + 8);
                al[mi][0] = *(const uint32_t*)(sAl + br * SROW + kcol);
                al[mi][1] = *(const uint32_t*)(sAl + (br + 8) * SROW + kcol);
                al[mi][2] = *(const uint32_t*)(sAl + br * SROW + kcol + 8);
                al[mi][3] = *(const uint32_t*)(sAl + (br + 8) * SROW + kcol + 8);
            }
#pragma unroll
            for (int ni = 0; ni < 8; ++ni) {
                int nr = wn * 64 + ni * 8 + r;
                int kcol = kb + c2 * 2;
                uint32_t bh[2], bl[2];
                bh[0] = *(const uint32_t*)(sBh + nr * SROW + kcol);
                bh[1] = *(const uint32_t*)(sBh + nr * SROW + kcol + 8);
                bl[0] = *(const uint32_t*)(sBl + nr * SROW + kcol);
                bl[1] = *(const uint32_t*)(sBl + nr * SROW + kcol + 8);
#pragma unroll
                for (int mi = 0; mi < 2; ++mi) {
                    MMA_BF16(acc[mi][ni], ah[mi], bh);
                    MMA_BF16(acc[mi][ni], al[mi], bh);
                    MMA_BF16(acc[mi][ni], ah[mi], bl);
                }
            }
        }
        if (pf) {
            sts_a(sn, av, tid);
            asm volatile("cp.async.wait_group 0;" ::: "memory");
        }
        __syncthreads();
    }

    // epilogue: write C (fp16) + fused attention dots (fp32-exact)
    float sh[2][2][2];
    float dh[2][2][2];
#pragma unroll
    for (int mi = 0; mi < 2; ++mi)
#pragma unroll
        for (int rh = 0; rh < 2; ++rh)
#pragma unroll
            for (int hl = 0; hl < 2; ++hl) { sh[mi][rh][hl] = 0.f; dh[mi][rh][hl] = 0.f; }

#pragma unroll
    for (int mi = 0; mi < 2; ++mi) {
        int gm0 = m0 + wm * 32 + mi * 16 + r;
#pragma unroll
        for (int ni = 0; ni < 8; ++ni) {
            int col = n0 + wn * 64 + ni * 8 + c2 * 2;
            int hl = ni >> 2;
            float as0 = __ldg(att_s + col), as1 = __ldg(att_s + col + 1);
            float ad0 = __ldg(att_d + col), ad1 = __ldg(att_d + col + 1);
            sh[mi][0][hl] += acc[mi][ni][0] * as0 + acc[mi][ni][1] * as1;
            dh[mi][0][hl] += acc[mi][ni][0] * ad0 + acc[mi][ni][1] * ad1;
            sh[mi][1][hl] += acc[mi][ni][2] * as0 + acc[mi][ni][3] * as1;
            dh[mi][1][hl] += acc[mi][ni][2] * ad0 + acc[mi][ni][3] * ad1;
            if (gm0 < M)
                *(__half2*)(Ch + (size_t)gm0 * HC + col) =
                    __float22half2_rn(make_float2(acc[mi][ni][0], acc[mi][ni][1]));
            if (gm0 + 8 < M)
                *(__half2*)(Ch + (size_t)(gm0 + 8) * HC + col) =
                    __float22half2_rn(make_float2(acc[mi][ni][2], acc[mi][ni][3]));
        }
    }
#pragma unroll
    for (int mi = 0; mi < 2; ++mi)
#pragma unroll
        for (int rh = 0; rh < 2; ++rh)
#pragma unroll
            for (int hl = 0; hl < 2; ++hl) {
                sh[mi][rh][hl] += __shfl_xor_sync(0xffffffffu, sh[mi][rh][hl], 1);
                sh[mi][rh][hl] += __shfl_xor_sync(0xffffffffu, sh[mi][rh][hl], 2);
                dh[mi][rh][hl] += __shfl_xor_sync(0xffffffffu, dh[mi][rh][hl], 1);
                dh[mi][rh][hl] += __shfl_xor_sync(0xffffffffu, dh[mi][rh][hl], 2);
            }
    if (c2 == 0) {
        int hb = (n0 >> 5) + wn * 2;
#pragma unroll
        for (int mi = 0; mi < 2; ++mi) {
#pragma unroll
            for (int rh = 0; rh < 2; ++rh) {
                int gm = m0 + wm * 32 + mi * 16 + r + rh * 8;
                if (gm < M) {
#pragma unroll
                    for (int hl = 0; hl < 2; ++hl) {
                        pas[(size_t)gm * 8 + hb + hl]  = sh[mi][rh][hl];
                        pad_[(size_t)gm * 8 + hb + hl] = dh[mi][rh][hl];
                    }
                }
            }
        }
    }
}

// ---------------- fused per-dst aggregation (fp16 feature gathers, [d0,d1)) ------
__device__ __forceinline__ void acc_fp16(uint4 raw, float w, float* a) {
    const __half2* p = (const __half2*)&raw;
#pragma unroll
    for (int j = 0; j < 4; ++j) {
        float2 f = __half22float2(p[j]);
        a[2 * j]     += w * f.x;
        a[2 * j + 1] += w * f.y;
    }
}

__global__ __launch_bounds__(512) void gat_aggregate(
    const int* __restrict__ rowptr, const int* __restrict__ rowend,
    const int* __restrict__ adj,
    const float* __restrict__ pas, const float* __restrict__ pad_,
    const __half* __restrict__ hlinh, const float* __restrict__ bias,
    float* __restrict__ hout, __half* __restrict__ hout16, int d0, int d1,
    const float* __restrict__ Wn, const float* __restrict__ bn,
    float* __restrict__ npred)
{
    int d = d0 + ((blockIdx.x * blockDim.x + threadIdx.x) >> 5);
    int lane = threadIdx.x & 31;
    if (d >= d1) return;
    int row0 = rowptr[d], row1 = rowend[d];
    int h = lane & 7;
    float padv = pad_[(size_t)d * 8 + h];
    int hsrc = lane >> 2;

    float ssum = 0.0f;
    float a[8];
#pragma unroll
    for (int j = 0; j < 8; ++j) a[j] = 0.0f;

    int i = row0;
    for (; i + 4 <= row1; i += 4) {
        int s0 = __ldg(adj + i),     s1 = __ldg(adj + i + 1);
        int s2 = __ldg(adj + i + 2), s3 = __ldg(adj + i + 3);
        float q0 = pas[(size_t)s0 * 8 + h];
        float q1 = pas[(size_t)s1 * 8 + h];
        float q2 = pas[(size_t)s2 * 8 + h];
        float q3 = pas[(size_t)s3 * 8 + h];
        uint4 r0 = *(const uint4*)(hlinh + (size_t)s0 * HC + lane * 8);
        uint4 r1 = *(const uint4*)(hlinh + (size_t)s1 * HC + lane * 8);
        uint4 r2 = *(const uint4*)(hlinh + (size_t)s2 * HC + lane * 8);
        uint4 r3 = *(const uint4*)(hlinh + (size_t)s3 * HC + lane * 8);
        float e0 = __expf(leaky(q0 + padv));
        float e1 = __expf(leaky(q1 + padv));
        float e2 = __expf(leaky(q2 + padv));
        float e3 = __expf(leaky(q3 + padv));
        ssum += (e0 + e1) + (e2 + e3);
        float w0 = __shfl_sync(0xffffffffu, e0, hsrc);
        float w1 = __shfl_sync(0xffffffffu, e1, hsrc);
        float w2 = __shfl_sync(0xffffffffu, e2, hsrc);
        float w3 = __shfl_sync(0xffffffffu, e3, hsrc);
        acc_fp16(r0, w0, a);
        acc_fp16(r1, w1, a);
        acc_fp16(r2, w2, a);
        acc_fp16(r3, w3, a);
    }
    for (; i < row1; ++i) {
        int s0 = __ldg(adj + i);
        float e0 = __expf(leaky(pas[(size_t)s0 * 8 + h] + padv));
        ssum += e0;
        float w0 = __shfl_sync(0xffffffffu, e0, hsrc);
        uint4 r0 = *(const uint4*)(hlinh + (size_t)s0 * HC + lane * 8);
        acc_fp16(r0, w0, a);
    }
    float denom = __shfl_sync(0xffffffffu, ssum, hsrc) + 1e-16f;
    float inv = 1.0f / denom;

    const float4* bp = (const float4*)(bias + lane * 8);
    float4 b0 = bp[0], b1 = bp[1];
    float4 o0, o1;
    o0.x = fmaxf(a[0] * inv + b0.x, 0.f); o0.y = fmaxf(a[1] * inv + b0.y, 0.f);
    o0.z = fmaxf(a[2] * inv + b0.z, 0.f); o0.w = fmaxf(a[3] * inv + b0.w, 0.f);
    o1.x = fmaxf(a[4] * inv + b1.x, 0.f); o1.y = fmaxf(a[5] * inv + b1.y, 0.f);
    o1.z = fmaxf(a[6] * inv + b1.z, 0.f); o1.w = fmaxf(a[7] * inv + b1.w, 0.f);
    float4* op = (float4*)(hout + (size_t)d * HC + lane * 8);
    op[0] = o0; op[1] = o1;

    if (hout16) {
        __half2 hv[4];
        hv[0] = __float22half2_rn(make_float2(o0.x, o0.y));
        hv[1] = __float22half2_rn(make_float2(o0.z, o0.w));
        hv[2] = __float22half2_rn(make_float2(o1.x, o1.y));
        hv[3] = __float22half2_rn(make_float2(o1.z, o1.w));
        *(uint4*)(hout16 + (size_t)d * HC + lane * 8) = *(const uint4*)hv;
    }

    if (npred) {
        const float4* wp = (const float4*)(Wn + lane * 8);
        float4 w0 = wp[0], w1 = wp[1];
        float np = o0.x * w0.x + o0.y * w0.y + o0.z * w0.z + o0.w * w0.w
                 + o1.x * w1.x + o1.y * w1.y + o1.z * w1.z + o1.w * w1.w;
#pragma unroll
        for (int o = 16; o; o >>= 1) np += __shfl_down_sync(0xffffffffu, np, o);
        if (lane == 0) npred[d] = np + bn[0];
    }
}

// ---------------- edge head: dst side fp32-exact, src gathers fp16 ----------------
__global__ __launch_bounds__(512) void edge_pred_csr(
    const int* __restrict__ rowptr, const int* __restrict__ rowend,
    const int* __restrict__ adj,
    const int* __restrict__ eid, const float* __restrict__ h,
    const __half* __restrict__ h16,
    const float* __restrict__ We, const float* __restrict__ be,
    float* __restrict__ out, int N)
{
    int d = (blockIdx.x * blockDim.x + threadIdx.x) >> 5;
    int lane = threadIdx.x & 31;
    if (d >= N) return;
    int row0 = rowptr[d] + 1;      // skip self loop
    int row1 = rowend[d];
    if (row0 >= row1) return;

    const float4* hdp = (const float4*)(h + (size_t)d * HC + lane * 8);
    const float4* wep = (const float4*)(We + lane * 8);
    float4 hd0 = hdp[0], hd1 = hdp[1];
    float4 w0 = wep[0],  w1 = wep[1];
    float g[8] = { hd0.x * w0.x, hd0.y * w0.y, hd0.z * w0.z, hd0.w * w0.w,
                   hd1.x * w1.x, hd1.y * w1.y, hd1.z * w1.z, hd1.w * w1.w };
    float bev = be[0];

    int p = row0;
    for (; p + 2 <= row1; p += 2) {
        int s0 = __ldg(adj + p), s1 = __ldg(adj + p + 1);
        uint4 ra = *(const uint4*)(h16 + (size_t)s0 * HC + lane * 8);
        uint4 rb = *(const uint4*)(h16 + (size_t)s1 * HC + lane * 8);
        const __half2* pa = (const __half2*)&ra;
        const __half2* pb = (const __half2*)&rb;
        float acc0 = 0.f, acc1 = 0.f;
#pragma unroll
        for (int j = 0; j < 4; ++j) {
            float2 fa = __half22float2(pa[j]);
            float2 fb = __half22float2(pb[j]);
            acc0 += fa.x * g[2 * j] + fa.y * g[2 * j + 1];
            acc1 += fb.x * g[2 * j] + fb.y * g[2 * j + 1];
        }
#pragma unroll
        for (int o = 16; o; o >>= 1) {
            acc0 += __shfl_down_sync(0xffffffffu, acc0, o);
            acc1 += __shfl_down_sync(0xffffffffu, acc1, o);
        }
        if (lane == 0) {
            out[__ldg(eid + p)]     = acc0 + bev;
            out[__ldg(eid + p + 1)] = acc1 + bev;
        }
    }
    if (p < row1) {
        int s = __ldg(adj + p);
        uint4 ra = *(const uint4*)(h16 + (size_t)s * HC + lane * 8);
        const __half2* pa = (const __half2*)&ra;
        float acc = 0.f;
#pragma unroll
        for (int j = 0; j < 4; ++j) {
            float2 fa = __half22float2(pa[j]);
            acc += fa.x * g[2 * j] + fa.y * g[2 * j + 1];
        }
#pragma unroll
        for (int o = 16; o; o >>= 1) acc += __shfl_down_sync(0xffffffffu, acc, o);
        if (lane == 0) out[__ldg(eid + p)] = acc + bev;
    }
}

// ---------------- host ----------------
static cudaStream_t g_s2 = nullptr;
static cudaEvent_t  g_ev_fork = nullptr, g_ev_join = nullptr;
static cudaEvent_t  g_evA = nullptr, g_evB = nullptr;

extern "C" void kernel_launch(void* const* d_in, const int* in_sizes, int n_in,
                              void* d_out, int out_size)
{
    if (!g_s2) {
        cudaStreamCreateWithFlags(&g_s2, cudaStreamNonBlocking);
        cudaEventCreateWithFlags(&g_ev_fork, cudaEventDisableTiming);
        cudaEventCreateWithFlags(&g_ev_join, cudaEventDisableTiming);
        cudaEventCreateWithFlags(&g_evA, cudaEventDisableTiming);
        cudaEventCreateWithFlags(&g_evB, cudaEventDisableTiming);
    }

    const float* x   = (const float*)d_in[0];
    const int*   ei  = (const int*)d_in[1];
    const float* W1  = (const float*)d_in[3];
    const float* as1 = (const float*)d_in[4];
    const float* ad1 = (const float*)d_in[5];
    const float* b1  = (const float*)d_in[6];
    const float* W2  = (const float*)d_in[7];
    const float* as2 = (const float*)d_in[8];
    const float* ad2 = (const float*)d_in[9];
    const float* b2  = (const float*)d_in[10];
    const float* We  = (const float*)d_in[11];
    const float* be  = (const float*)d_in[12];
    const float* Wn  = (const float*)d_in[13];
    const float* bn  = (const float*)d_in[14];

    int N = in_sizes[0] / 128;
    int E = in_sizes[1] / 2;
    int Nh = N / 2;

    float *h1, *pas1, *pad1, *pas2, *pad2;
    __half *hl1, *hl2, *h16;
    int *deg, *rowptr, *rowend, *cursor, *adj, *eid, *counter;
    __nv_bfloat16 *wthi1, *wtlo1, *wthi2, *wtlo2;
    cudaGetSymbolAddress((void**)&hl1,     g_hlinh1);
    cudaGetSymbolAddress((void**)&hl2,     g_hlinh2);
    cudaGetSymbolAddress((void**)&h1,      g_h1);
    cudaGetSymbolAddress((void**)&h16,     g_h16);
    cudaGetSymbolAddress((void**)&pas1,    g_as1);
    cudaGetSymbolAddress((void**)&pad1,    g_ad1);
    cudaGetSymbolAddress((void**)&pas2,    g_as2);
    cudaGetSymbolAddress((void**)&pad2,    g_ad2);
    cudaGetSymbolAddress((void**)&deg,     g_deg);
    cudaGetSymbolAddress((void**)&rowptr,  g_rowptr);
    cudaGetSymbolAddress((void**)&rowend,  g_rowend);
    cudaGetSymbolAddress((void**)&cursor,  g_cursor);
    cudaGetSymbolAddress((void**)&adj,     g_adj);
    cudaGetSymbolAddress((void**)&eid,     g_eid);
    cudaGetSymbolAddress((void**)&counter, g_counter);
    cudaGetSymbolAddress((void**)&wthi1,   g_wthi1);
    cudaGetSymbolAddress((void**)&wtlo1,   g_wtlo1);
    cudaGetSymbolAddress((void**)&wthi2,   g_wthi2);
    cudaGetSymbolAddress((void**)&wtlo2,   g_wtlo2);

    cudaFuncSetAttribute(gemm_mma, cudaFuncAttributeMaxDynamicSharedMemorySize, GEMM_SMEM);

    // ---- fork: CSR build + layer-2 weight convert on side stream
    cudaEventRecord(g_ev_fork, 0);
    cudaStreamWaitEvent(g_s2, g_ev_fork, 0);
    cudaMemsetAsync(deg, 0, (size_t)N * sizeof(int), g_s2);
    cudaMemsetAsync(counter, 0, sizeof(int), g_s2);
    count_kernel<<<(E + 511) / 512, 512, 0, g_s2>>>(ei, deg, E);
    alloc_kernel<<<(N + 511) / 512, 512, 0, g_s2>>>(deg, rowptr, rowend, counter,
                                                    adj, cursor, N);
    edge_place_kernel<<<(E + 511) / 512, 512, 0, g_s2>>>(ei, cursor, adj, eid, E);
    wt_convert<<<(256 * HC + 255) / 256, 256, 0, g_s2>>>(W2, wthi2, wtlo2, 256);
    cudaEventRecord(g_ev_join, g_s2);

    // ---- main: layer-1 GEMM (full)
    wt_convert<<<(128 * HC + 255) / 256, 256>>>(W1, wthi1, wtlo1, 128);
    {
        dim3 gg(2, (N + 127) / 128);
        gemm_mma<<<gg, 256, GEMM_SMEM>>>(x, wthi1, wtlo1, hl1, N, 128,
                                         as1, ad1, pas1, pad1);
    }
    cudaStreamWaitEvent(0, g_ev_join, 0);

    float* out = (float*)d_out;

    // ---- layer-1 aggregate chunk 0
    gat_aggregate<<<((long long)Nh * 32 + 511) / 512, 512>>>(
        rowptr, rowend, adj, pas1, pad1, hl1, b1, h1, nullptr, 0, Nh,
        nullptr, nullptr, nullptr);
    cudaEventRecord(g_evA, 0);

    // side: layer-1 aggregate chunk 1 (overlaps gemm2 chunk 0)
    cudaStreamWaitEvent(g_s2, g_evA, 0);
    gat_aggregate<<<((long long)(N - Nh) * 32 + 511) / 512, 512, 0, g_s2>>>(
        rowptr, rowend, adj, pas1, pad1, hl1, b1, h1, nullptr, Nh, N,
        nullptr, nullptr, nullptr);
    cudaEventRecord(g_evB, g_s2);

    // main: layer-2 GEMM chunk 0
    {
        dim3 gg(2, (Nh + 127) / 128);
        gemm_mma<<<gg, 256, GEMM_SMEM>>>(h1, wthi2, wtlo2, hl2, Nh, 256,
                                         as2, ad2, pas2, pad2);
    }
    cudaStreamWaitEvent(0, g_evB, 0);
    // main: layer-2 GEMM chunk 1
    {
        int M1 = N - Nh;
        dim3 gg(2, (M1 + 127) / 128);
        gemm_mma<<<gg, 256, GEMM_SMEM>>>(
            h1 + (size_t)Nh * HC, wthi2, wtlo2, hl2 + (size_t)Nh * HC, M1, 256,
            as2, ad2, pas2 + (size_t)Nh * NH, pad2 + (size_t)Nh * NH);
    }

    // layer-2 aggregate (full) + fp16 h copy + fused node head
    gat_aggregate<<<((long long)N * 32 + 511) / 512, 512>>>(
        rowptr, rowend, adj, pas2, pad2, hl2, b2, h1, h16, 0, N,
        Wn, bn, out + E);

    edge_pred_csr<<<((long long)N * 32 + 511) / 512, 512>>>(
        rowptr, rowend, adj, eid, h1, h16, We, be, out, N);
}

// round 17
// speedup vs baseline: 1.1380x; 1.1380x over previous
#include <cuda_runtime.h>
#include <cuda_bf16.h>
#include <cuda_fp16.h>
#include <cmath>
#include <cstdint>

#define NMAX 50000
#define EMAX 800000
#define HC   256
#define NH   8
#define NEG  0.2f

// ---------------- scratch (static device globals; no allocation) ----------------
__device__ __half g_hlinh1[NMAX * HC];
__device__ __half g_hlinh2[NMAX * HC];
__device__ float g_h1  [NMAX * HC];
__device__ __half g_h16 [NMAX * HC];
__device__ float g_as1 [NMAX * NH];
__device__ float g_ad1 [NMAX * NH];
__device__ float g_as2 [NMAX * NH];
__device__ float g_ad2 [NMAX * NH];
__device__ int   g_deg [NMAX];
__device__ int   g_rowptr[NMAX];
__device__ int   g_rowend[NMAX];
__device__ int   g_cursor[NMAX];
__device__ int   g_adj [EMAX + NMAX];
__device__ int   g_eid [EMAX + NMAX];
__device__ int   g_counter;
__device__ __nv_bfloat16 g_wthi1[HC * 128];
__device__ __nv_bfloat16 g_wtlo1[HC * 128];
__device__ __nv_bfloat16 g_wthi2[HC * HC];
__device__ __nv_bfloat16 g_wtlo2[HC * HC];

__device__ __forceinline__ float leaky(float v) { return v > 0.0f ? v : NEG * v; }

__device__ __forceinline__ void cp_async16(void* dst, const void* src) {
    uint32_t d = (uint32_t)__cvta_generic_to_shared(dst);
    asm volatile("cp.async.cg.shared.global [%0], [%1], 16;" :: "r"(d), "l"(src));
}

// ---------------- CSR build (scan-free, merged kernels) ----------------
__global__ __launch_bounds__(512) void count_kernel(
    const int* __restrict__ ei, int* __restrict__ deg, int E)
{
    int e = blockIdx.x * blockDim.x + threadIdx.x;
    if (e < E) atomicAdd(&deg[__ldg(ei + E + e)], 1);
}

// alloc + self-place fused; deg holds real-edge counts (0-init), +1 self loop here
__global__ __launch_bounds__(512) void alloc_kernel(
    const int* __restrict__ deg, int* __restrict__ rowptr, int* __restrict__ rowend,
    int* __restrict__ counter, int* __restrict__ adj, int* __restrict__ cursor, int N)
{
    int d = blockIdx.x * blockDim.x + threadIdx.x;
    int lane = threadIdx.x & 31;
    int v = (d < N) ? (deg[d] + 1) : 0;
    int pre = v;
#pragma unroll
    for (int o = 1; o < 32; o <<= 1) {
        int t = __shfl_up_sync(0xffffffffu, pre, o);
        if (lane >= o) pre += t;
    }
    int wsum = __shfl_sync(0xffffffffu, pre, 31);
    int base = 0;
    if (lane == 31) base = atomicAdd(counter, wsum);
    base = __shfl_sync(0xffffffffu, base, 31);
    if (d < N) {
        int start = base + pre - v;
        rowptr[d] = start;
        rowend[d] = start + v;
        adj[start] = d;           // self loop first
        cursor[d] = start + 1;
    }
}

__global__ __launch_bounds__(512) void edge_place_kernel(
    const int* __restrict__ ei,
    int* __restrict__ cursor, int* __restrict__ adj,
    int* __restrict__ eid, int E)
{
    int e = blockIdx.x * blockDim.x + threadIdx.x;
    if (e < E) {
        int dst = __ldg(ei + E + e);
        int p = atomicAdd(&cursor[dst], 1);
        adj[p] = __ldg(ei + e);
        eid[p] = e;
    }
}

// ---------------- weight transpose + bf16 hi/lo split ----------------
__global__ void wt_convert(const float* __restrict__ W,
                           __nv_bfloat16* __restrict__ hi,
                           __nv_bfloat16* __restrict__ lo, int K)
{
    int idx = blockIdx.x * blockDim.x + threadIdx.x;
    if (idx >= K * HC) return;
    int k = idx >> 8, n = idx & 255;
    float v = W[idx];
    __nv_bfloat16 h = __float2bfloat16(v);
    hi[(size_t)n * K + k] = h;
    lo[(size_t)n * K + k] = __float2bfloat16(v - __bfloat162float(h));
}

// ---------------- pipelined mma.sync bf16x2-split GEMM (BK=32, 2 CTAs/SM) -------
#define SROW 40
#define OAH 0
#define OAL 10240
#define OBH 20480
#define OBL 30720
#define STAGE 40960
#define GEMM_SMEM (2 * STAGE)

#define MMA_BF16(d, a, b)                                                     \
    asm volatile(                                                             \
        "mma.sync.aligned.m16n8k16.row.col.f32.bf16.bf16.f32 "                \
        "{%0,%1,%2,%3}, {%4,%5,%6,%7}, {%8,%9}, {%0,%1,%2,%3};"               \
        : "+f"(d[0]), "+f"(d[1]), "+f"(d[2]), "+f"(d[3])                      \
        : "r"(a[0]), "r"(a[1]), "r"(a[2]), "r"(a[3]), "r"(b[0]), "r"(b[1]))

__device__ __forceinline__ void load_a_regs(
    float4* av, const float* A, int M, int K, int m0, int kc, int tid)
{
#pragma unroll
    for (int it = 0; it < 4; ++it) {
        int p = tid + it * 256;
        int row = p >> 3, c4 = p & 7;
        av[it] = (m0 + row < M)
            ? *(const float4*)(A + (size_t)(m0 + row) * K + kc + c4 * 4)
            : make_float4(0.f, 0.f, 0.f, 0.f);
    }
}

__device__ __forceinline__ void sts_a(char* sb, const float4* av, int tid)
{
    __nv_bfloat16* sAh = (__nv_bfloat16*)(sb + OAH);
    __nv_bfloat16* sAl = (__nv_bfloat16*)(sb + OAL);
#pragma unroll
    for (int it = 0; it < 4; ++it) {
        int p = tid + it * 256;
        int row = p >> 3, c4 = p & 7;
        float4 v = av[it];
        __nv_bfloat16 h0 = __float2bfloat16(v.x), h1 = __float2bfloat16(v.y);
        __nv_bfloat16 h2 = __float2bfloat16(v.z), h3 = __float2bfloat16(v.w);
        __nv_bfloat16 l0 = __float2bfloat16(v.x - __bfloat162float(h0));
        __nv_bfloat16 l1 = __float2bfloat16(v.y - __bfloat162float(h1));
        __nv_bfloat16 l2 = __float2bfloat16(v.z - __bfloat162float(h2));
        __nv_bfloat16 l3 = __float2bfloat16(v.w - __bfloat162float(h3));
        int o = row * SROW + c4 * 4;
        *(__nv_bfloat162*)(sAh + o)     = __halves2bfloat162(h0, h1);
        *(__nv_bfloat162*)(sAh + o + 2) = __halves2bfloat162(h2, h3);
        *(__nv_bfloat162*)(sAl + o)     = __halves2bfloat162(l0, l1);
        *(__nv_bfloat162*)(sAl + o + 2) = __halves2bfloat162(l2, l3);
    }
}

__device__ __forceinline__ void cp_b(
    char* sb, const __nv_bfloat16* Bh, const __nv_bfloat16* Bl,
    int K, int n0, int kc, int tid)
{
#pragma unroll
    for (int it = 0; it < 2; ++it) {
        int p = tid + it * 256;
        int row = p >> 2, q = p & 3;
        cp_async16(sb + OBH + row * (SROW * 2) + q * 16,
                   (const char*)(Bh + (size_t)(n0 + row) * K + kc) + q * 16);
        cp_async16(sb + OBL + row * (SROW * 2) + q * 16,
                   (const char*)(Bl + (size_t)(n0 + row) * K + kc) + q * 16);
    }
    asm volatile("cp.async.commit_group;" ::: "memory");
}

__global__ __launch_bounds__(256, 2) void gemm_mma(
    const float* __restrict__ A, const __nv_bfloat16* __restrict__ Bh,
    const __nv_bfloat16* __restrict__ Bl, __half* __restrict__ Ch,
    int M, int K,
    const float* __restrict__ att_s, const float* __restrict__ att_d,
    float* __restrict__ pas, float* __restrict__ pad_)
{
    extern __shared__ char smem[];
    int tid = threadIdx.x, wid = tid >> 5, lane = tid & 31;
    int wm = wid & 3, wn = wid >> 2;
    int m0 = blockIdx.y * 128;
    int n0 = blockIdx.x * 128;

    float acc[2][8][4];
#pragma unroll
    for (int mi = 0; mi < 2; ++mi)
#pragma unroll
        for (int ni = 0; ni < 8; ++ni)
#pragma unroll
            for (int q = 0; q < 4; ++q) acc[mi][ni][q] = 0.0f;

    int r = lane >> 2, c2 = lane & 3;
    int nch = K >> 5;

    float4 av[4];
    load_a_regs(av, A, M, K, m0, 0, tid);
    cp_b(smem, Bh, Bl, K, n0, 0, tid);
    sts_a(smem, av, tid);
    asm volatile("cp.async.wait_group 0;" ::: "memory");
    __syncthreads();

    for (int c = 0; c < nch; ++c) {
        char* sb = smem + (c & 1) * STAGE;
        char* sn = smem + ((c + 1) & 1) * STAGE;
        bool pf = (c + 1) < nch;
        if (pf) {
            load_a_regs(av, A, M, K, m0, (c + 1) * 32, tid);
            cp_b(sn, Bh, Bl, K, n0, (c + 1) * 32, tid);
        }

        __nv_bfloat16* sAh = (__nv_bfloat16*)(sb + OAH);
        __nv_bfloat16* sAl = (__nv_bfloat16*)(sb + OAL);
        __nv_bfloat16* sBh = (__nv_bfloat16*)(sb + OBH);
        __nv_bfloat16* sBl = (__nv_bfloat16*)(sb + OBL);

#pragma unroll
        for (int k16 = 0; k16 < 2; ++k16) {
            int kb = k16 * 16;
            uint32_t ah[2][4], al[2][4];
#pragma unroll
            for (int mi = 0; mi < 2; ++mi) {
                int br = wm * 32 + mi * 16 + r;
                int kcol = kb + c2 * 2;
                ah[mi][0] = *(const uint32_t*)(sAh + br * SROW + kcol);
                ah[mi][1] = *(const uint32_t*)(sAh + (br + 8) * SROW + kcol);
                ah[mi][2] = *(const uint32_t*)(sAh + br * SROW + kcol + 8);
                ah[mi][3] = *(const uint32_t*)(sAh + (br + 8) * SROW + kcol + 8);
                al[mi][0] = *(const uint32_t*)(sAl + br * SROW + kcol);
                al[mi][1] = *(const uint32_t*)(sAl + (br + 8) * SROW + kcol);
                al[mi][2] = *(const uint32_t*)(sAl + br * SROW + kcol + 8);
                al[mi][3] = *(const uint32_t*)(sAl + (br + 8) * SROW + kcol + 8);
            }
#pragma unroll
            for (int ni = 0; ni < 8; ++ni) {
                int nr = wn * 64 + ni * 8 + r;
                int kcol = kb + c2 * 2;
                uint32_t bh[2], bl[2];
                bh[0] = *(const uint32_t*)(sBh + nr * SROW + kcol);
                bh[1] = *(const uint32_t*)(sBh + nr * SROW + kcol + 8);
                bl[0] = *(const uint32_t*)(sBl + nr * SROW + kcol);
                bl[1] = *(const uint32_t*)(sBl + nr * SROW + kcol + 8);
#pragma unroll
                for (int mi = 0; mi < 2; ++mi) {
                    MMA_BF16(acc[mi][ni], ah[mi], bh);
                    MMA_BF16(acc[mi][ni], al[mi], bh);
                    MMA_BF16(acc[mi][ni], ah[mi], bl);
                }
            }
        }
        if (pf) {
            sts_a(sn, av, tid);
            asm volatile("cp.async.wait_group 0;" ::: "memory");
        }
        __syncthreads();
    }

    // epilogue: write C (fp16) + fused attention dots (fp32-exact)
    float sh[2][2][2];
    float dh[2][2][2];
#pragma unroll
    for (int mi = 0; mi < 2; ++mi)
#pragma unroll
        for (int rh = 0; rh < 2; ++rh)
#pragma unroll
            for (int hl = 0; hl < 2; ++hl) { sh[mi][rh][hl] = 0.f; dh[mi][rh][hl] = 0.f; }

#pragma unroll
    for (int mi = 0; mi < 2; ++mi) {
        int gm0 = m0 + wm * 32 + mi * 16 + r;
#pragma unroll
        for (int ni = 0; ni < 8; ++ni) {
            int col = n0 + wn * 64 + ni * 8 + c2 * 2;
            int hl = ni >> 2;
            float as0 = __ldg(att_s + col), as1 = __ldg(att_s + col + 1);
            float ad0 = __ldg(att_d + col), ad1 = __ldg(att_d + col + 1);
            sh[mi][0][hl] += acc[mi][ni][0] * as0 + acc[mi][ni][1] * as1;
            dh[mi][0][hl] += acc[mi][ni][0] * ad0 + acc[mi][ni][1] * ad1;
            sh[mi][1][hl] += acc[mi][ni][2] * as0 + acc[mi][ni][3] * as1;
            dh[mi][1][hl] += acc[mi][ni][2] * ad0 + acc[mi][ni][3] * ad1;
            if (gm0 < M)
                *(__half2*)(Ch + (size_t)gm0 * HC + col) =
                    __float22half2_rn(make_float2(acc[mi][ni][0], acc[mi][ni][1]));
            if (gm0 + 8 < M)
                *(__half2*)(Ch + (size_t)(gm0 + 8) * HC + col) =
                    __float22half2_rn(make_float2(acc[mi][ni][2], acc[mi][ni][3]));
        }
    }
#pragma unroll
    for (int mi = 0; mi < 2; ++mi)
#pragma unroll
        for (int rh = 0; rh < 2; ++rh)
#pragma unroll
            for (int hl = 0; hl < 2; ++hl) {
                sh[mi][rh][hl] += __shfl_xor_sync(0xffffffffu, sh[mi][rh][hl], 1);
                sh[mi][rh][hl] += __shfl_xor_sync(0xffffffffu, sh[mi][rh][hl], 2);
                dh[mi][rh][hl] += __shfl_xor_sync(0xffffffffu, dh[mi][rh][hl], 1);
                dh[mi][rh][hl] += __shfl_xor_sync(0xffffffffu, dh[mi][rh][hl], 2);
            }
    if (c2 == 0) {
        int hb = (n0 >> 5) + wn * 2;
#pragma unroll
        for (int mi = 0; mi < 2; ++mi) {
#pragma unroll
            for (int rh = 0; rh < 2; ++rh) {
                int gm = m0 + wm * 32 + mi * 16 + r + rh * 8;
                if (gm < M) {
#pragma unroll
                    for (int hl = 0; hl < 2; ++hl) {
                        pas[(size_t)gm * 8 + hb + hl]  = sh[mi][rh][hl];
                        pad_[(size_t)gm * 8 + hb + hl] = dh[mi][rh][hl];
                    }
                }
            }
        }
    }
}

// ---------------- fused per-dst aggregation (fp16 feature gathers, [d0,d1)) ------
__device__ __forceinline__ void acc_fp16(uint4 raw, float w, float* a) {
    const __half2* p = (const __half2*)&raw;
#pragma unroll
    for (int j = 0; j < 4; ++j) {
        float2 f = __half22float2(p[j]);
        a[2 * j]     += w * f.x;
        a[2 * j + 1] += w * f.y;
    }
}

__global__ __launch_bounds__(256) void gat_aggregate(
    const int* __restrict__ rowptr, const int* __restrict__ rowend,
    const int* __restrict__ adj,
    const float* __restrict__ pas, const float* __restrict__ pad_,
    const __half* __restrict__ hlinh, const float* __restrict__ bias,
    float* __restrict__ hout, __half* __restrict__ hout16, int d0, int d1,
    const float* __restrict__ Wn, const float* __restrict__ bn,
    float* __restrict__ npred)
{
    int d = d0 + ((blockIdx.x * blockDim.x + threadIdx.x) >> 5);
    int lane = threadIdx.x & 31;
    if (d >= d1) return;
    int row0 = rowptr[d], row1 = rowend[d];
    int h = lane & 7;
    float padv = pad_[(size_t)d * 8 + h];
    int hsrc = lane >> 2;

    float ssum = 0.0f;
    float a[8];
#pragma unroll
    for (int j = 0; j < 8; ++j) a[j] = 0.0f;

    int i = row0;
    for (; i + 4 <= row1; i += 4) {
        int s0 = __ldg(adj + i),     s1 = __ldg(adj + i + 1);
        int s2 = __ldg(adj + i + 2), s3 = __ldg(adj + i + 3);
        float q0 = pas[(size_t)s0 * 8 + h];
        float q1 = pas[(size_t)s1 * 8 + h];
        float q2 = pas[(size_t)s2 * 8 + h];
        float q3 = pas[(size_t)s3 * 8 + h];
        uint4 r0 = *(const uint4*)(hlinh + (size_t)s0 * HC + lane * 8);
        uint4 r1 = *(const uint4*)(hlinh + (size_t)s1 * HC + lane * 8);
        uint4 r2 = *(const uint4*)(hlinh + (size_t)s2 * HC + lane * 8);
        uint4 r3 = *(const uint4*)(hlinh + (size_t)s3 * HC + lane * 8);
        float e0 = __expf(leaky(q0 + padv));
        float e1 = __expf(leaky(q1 + padv));
        float e2 = __expf(leaky(q2 + padv));
        float e3 = __expf(leaky(q3 + padv));
        ssum += (e0 + e1) + (e2 + e3);
        float w0 = __shfl_sync(0xffffffffu, e0, hsrc);
        float w1 = __shfl_sync(0xffffffffu, e1, hsrc);
        float w2 = __shfl_sync(0xffffffffu, e2, hsrc);
        float w3 = __shfl_sync(0xffffffffu, e3, hsrc);
        acc_fp16(r0, w0, a);
        acc_fp16(r1, w1, a);
        acc_fp16(r2, w2, a);
        acc_fp16(r3, w3, a);
    }
    for (; i < row1; ++i) {
        int s0 = __ldg(adj + i);
        float e0 = __expf(leaky(pas[(size_t)s0 * 8 + h] + padv));
        ssum += e0;
        float w0 = __shfl_sync(0xffffffffu, e0, hsrc);
        uint4 r0 = *(const uint4*)(hlinh + (size_t)s0 * HC + lane * 8);
        acc_fp16(r0, w0, a);
    }
    float denom = __shfl_sync(0xffffffffu, ssum, hsrc) + 1e-16f;
    float inv = 1.0f / denom;

    const float4* bp = (const float4*)(bias + lane * 8);
    float4 b0 = bp[0], b1 = bp[1];
    float4 o0, o1;
    o0.x = fmaxf(a[0] * inv + b0.x, 0.f); o0.y = fmaxf(a[1] * inv + b0.y, 0.f);
    o0.z = fmaxf(a[2] * inv + b0.z, 0.f); o0.w = fmaxf(a[3] * inv + b0.w, 0.f);
    o1.x = fmaxf(a[4] * inv + b1.x, 0.f); o1.y = fmaxf(a[5] * inv + b1.y, 0.f);
    o1.z = fmaxf(a[6] * inv + b1.z, 0.f); o1.w = fmaxf(a[7] * inv + b1.w, 0.f);
    float4* op = (float4*)(hout + (size_t)d * HC + lane * 8);
    op[0] = o0; op[1] = o1;

    if (hout16) {
        __half2 hv[4];
        hv[0] = __float22half2_rn(make_float2(o0.x, o0.y));
        hv[1] = __float22half2_rn(make_float2(o0.z, o0.w));
        hv[2] = __float22half2_rn(make_float2(o1.x, o1.y));
        hv[3] = __float22half2_rn(make_float2(o1.z, o1.w));
        *(uint4*)(hout16 + (size_t)d * HC + lane * 8) = *(const uint4*)hv;
    }

    if (npred) {
        const float4* wp = (const float4*)(Wn + lane * 8);
        float4 w0 = wp[0], w1 = wp[1];
        float np = o0.x * w0.x + o0.y * w0.y + o0.z * w0.z + o0.w * w0.w
                 + o1.x * w1.x + o1.y * w1.y + o1.z * w1.z + o1.w * w1.w;
#pragma unroll
        for (int o = 16; o; o >>= 1) np += __shfl_down_sync(0xffffffffu, np, o);
        if (lane == 0) npred[d] = np + bn[0];
    }
}

// ---------------- edge head: dst side fp32-exact, src gathers fp16 ----------------
__global__ __launch_bounds__(256) void edge_pred_csr(
    const int* __restrict__ rowptr, const int* __restrict__ rowend,
    const int* __restrict__ adj,
    const int* __restrict__ eid, const float* __restrict__ h,
    const __half* __restrict__ h16,
    const float* __restrict__ We, const float* __restrict__ be,
    float* __restrict__ out, int N)
{
    int d = (blockIdx.x * blockDim.x + threadIdx.x) >> 5;
    int lane = threadIdx.x & 31;
    if (d >= N) return;
    int row0 = rowptr[d] + 1;      // skip self loop
    int row1 = rowend[d];
    if (row0 >= row1) return;

    const float4* hdp = (const float4*)(h + (size_t)d * HC + lane * 8);
    const float4* wep = (const float4*)(We + lane * 8);
    float4 hd0 = hdp[0], hd1 = hdp[1];
    float4 w0 = wep[0],  w1 = wep[1];
    float g[8] = { hd0.x * w0.x, hd0.y * w0.y, hd0.z * w0.z, hd0.w * w0.w,
                   hd1.x * w1.x, hd1.y * w1.y, hd1.z * w1.z, hd1.w * w1.w };
    float bev = be[0];

    int p = row0;
    for (; p + 2 <= row1; p += 2) {
        int s0 = __ldg(adj + p), s1 = __ldg(adj + p + 1);
        uint4 ra = *(const uint4*)(h16 + (size_t)s0 * HC + lane * 8);
        uint4 rb = *(const uint4*)(h16 + (size_t)s1 * HC + lane * 8);
        const __half2* pa = (const __half2*)&ra;
        const __half2* pb = (const __half2*)&rb;
        float acc0 = 0.f, acc1 = 0.f;
#pragma unroll
        for (int j = 0; j < 4; ++j) {
            float2 fa = __half22float2(pa[j]);
            float2 fb = __half22float2(pb[j]);
            acc0 += fa.x * g[2 * j] + fa.y * g[2 * j + 1];
            acc1 += fb.x * g[2 * j] + fb.y * g[2 * j + 1];
        }
#pragma unroll
        for (int o = 16; o; o >>= 1) {
            acc0 += __shfl_down_sync(0xffffffffu, acc0, o);
            acc1 += __shfl_down_sync(0xffffffffu, acc1, o);
        }
        if (lane == 0) {
            out[__ldg(eid + p)]     = acc0 + bev;
            out[__ldg(eid + p + 1)] = acc1 + bev;
        }
    }
    if (p < row1) {
        int s = __ldg(adj + p);
        uint4 ra = *(const uint4*)(h16 + (size_t)s * HC + lane * 8);
        const __half2* pa = (const __half2*)&ra;
        float acc = 0.f;
#pragma unroll
        for (int j = 0; j < 4; ++j) {
            float2 fa = __half22float2(pa[j]);
            acc += fa.x * g[2 * j] + fa.y * g[2 * j + 1];
        }
#pragma unroll
        for (int o = 16; o; o >>= 1) acc += __shfl_down_sync(0xffffffffu, acc, o);
        if (lane == 0) out[__ldg(eid + p)] = acc + bev;
    }
}

// ---------------- host ----------------
static cudaStream_t g_s2 = nullptr;
static cudaEvent_t  g_ev_fork = nullptr, g_ev_join = nullptr;
static cudaEvent_t  g_evA = nullptr, g_evB = nullptr;

extern "C" void kernel_launch(void* const* d_in, const int* in_sizes, int n_in,
                              void* d_out, int out_size)
{
    if (!g_s2) {
        cudaStreamCreateWithFlags(&g_s2, cudaStreamNonBlocking);
        cudaEventCreateWithFlags(&g_ev_fork, cudaEventDisableTiming);
        cudaEventCreateWithFlags(&g_ev_join, cudaEventDisableTiming);
        cudaEventCreateWithFlags(&g_evA, cudaEventDisableTiming);
        cudaEventCreateWithFlags(&g_evB, cudaEventDisableTiming);
    }

    const float* x   = (const float*)d_in[0];
    const int*   ei  = (const int*)d_in[1];
    const float* W1  = (const float*)d_in[3];
    const float* as1 = (const float*)d_in[4];
    const float* ad1 = (const float*)d_in[5];
    const float* b1  = (const float*)d_in[6];
    const float* W2  = (const float*)d_in[7];
    const float* as2 = (const float*)d_in[8];
    const float* ad2 = (const float*)d_in[9];
    const float* b2  = (const float*)d_in[10];
    const float* We  = (const float*)d_in[11];
    const float* be  = (const float*)d_in[12];
    const float* Wn  = (const float*)d_in[13];
    const float* bn  = (const float*)d_in[14];

    int N = in_sizes[0] / 128;
    int E = in_sizes[1] / 2;
    int Nh = N / 2;

    float *h1, *pas1, *pad1, *pas2, *pad2;
    __half *hl1, *hl2, *h16;
    int *deg, *rowptr, *rowend, *cursor, *adj, *eid, *counter;
    __nv_bfloat16 *wthi1, *wtlo1, *wthi2, *wtlo2;
    cudaGetSymbolAddress((void**)&hl1,     g_hlinh1);
    cudaGetSymbolAddress((void**)&hl2,     g_hlinh2);
    cudaGetSymbolAddress((void**)&h1,      g_h1);
    cudaGetSymbolAddress((void**)&h16,     g_h16);
    cudaGetSymbolAddress((void**)&pas1,    g_as1);
    cudaGetSymbolAddress((void**)&pad1,    g_ad1);
    cudaGetSymbolAddress((void**)&pas2,    g_as2);
    cudaGetSymbolAddress((void**)&pad2,    g_ad2);
    cudaGetSymbolAddress((void**)&deg,     g_deg);
    cudaGetSymbolAddress((void**)&rowptr,  g_rowptr);
    cudaGetSymbolAddress((void**)&rowend,  g_rowend);
    cudaGetSymbolAddress((void**)&cursor,  g_cursor);
    cudaGetSymbolAddress((void**)&adj,     g_adj);
    cudaGetSymbolAddress((void**)&eid,     g_eid);
    cudaGetSymbolAddress((void**)&counter, g_counter);
    cudaGetSymbolAddress((void**)&wthi1,   g_wthi1);
    cudaGetSymbolAddress((void**)&wtlo1,   g_wtlo1);
    cudaGetSymbolAddress((void**)&wthi2,   g_wthi2);
    cudaGetSymbolAddress((void**)&wtlo2,   g_wtlo2);

    cudaFuncSetAttribute(gemm_mma, cudaFuncAttributeMaxDynamicSharedMemorySize, GEMM_SMEM);

    // ---- fork: layer-2 weight convert FIRST, then CSR build, on side stream
    cudaEventRecord(g_ev_fork, 0);
    cudaStreamWaitEvent(g_s2, g_ev_fork, 0);
    wt_convert<<<(256 * HC + 255) / 256, 256, 0, g_s2>>>(W2, wthi2, wtlo2, 256);
    cudaMemsetAsync(deg, 0, (size_t)N * sizeof(int), g_s2);
    cudaMemsetAsync(counter, 0, sizeof(int), g_s2);
    count_kernel<<<(E + 511) / 512, 512, 0, g_s2>>>(ei, deg, E);
    alloc_kernel<<<(N + 511) / 512, 512, 0, g_s2>>>(deg, rowptr, rowend, counter,
                                                    adj, cursor, N);
    edge_place_kernel<<<(E + 511) / 512, 512, 0, g_s2>>>(ei, cursor, adj, eid, E);
    cudaEventRecord(g_ev_join, g_s2);

    // ---- main: layer-1 GEMM (full)
    wt_convert<<<(128 * HC + 255) / 256, 256>>>(W1, wthi1, wtlo1, 128);
    {
        dim3 gg(2, (N + 127) / 128);
        gemm_mma<<<gg, 256, GEMM_SMEM>>>(x, wthi1, wtlo1, hl1, N, 128,
                                         as1, ad1, pas1, pad1);
    }
    cudaStreamWaitEvent(0, g_ev_join, 0);

    float* out = (float*)d_out;

    // ---- layer-1 aggregate chunk 0
    gat_aggregate<<<((long long)Nh * 32 + 255) / 256, 256>>>(
        rowptr, rowend, adj, pas1, pad1, hl1, b1, h1, nullptr, 0, Nh,
        nullptr, nullptr, nullptr);
    cudaEventRecord(g_evA, 0);

    // side: layer-1 aggregate chunk 1 (overlaps gemm2 chunk 0)
    cudaStreamWaitEvent(g_s2, g_evA, 0);
    gat_aggregate<<<((long long)(N - Nh) * 32 + 255) / 256, 256, 0, g_s2>>>(
        rowptr, rowend, adj, pas1, pad1, hl1, b1, h1, nullptr, Nh, N,
        nullptr, nullptr, nullptr);
    cudaEventRecord(g_evB, g_s2);

    // main: layer-2 GEMM chunk 0
    {
        dim3 gg(2, (Nh + 127) / 128);
        gemm_mma<<<gg, 256, GEMM_SMEM>>>(h1, wthi2, wtlo2, hl2, Nh, 256,
                                         as2, ad2, pas2, pad2);
    }
    cudaStreamWaitEvent(0, g_evB, 0);
    // main: layer-2 GEMM chunk 1
    {
        int M1 = N - Nh;
        dim3 gg(2, (M1 + 127) / 128);
        gemm_mma<<<gg, 256, GEMM_SMEM>>>(
            h1 + (size_t)Nh * HC, wthi2, wtlo2, hl2 + (size_t)Nh * HC, M1, 256,
            as2, ad2, pas2 + (size_t)Nh * NH, pad2 + (size_t)Nh * NH);
    }

    // layer-2 aggregate (full) + fp16 h copy + fused node head
    gat_aggregate<<<((long long)N * 32 + 255) / 256, 256>>>(
        rowptr, rowend, adj, pas2, pad2, hl2, b2, h1, h16, 0, N,
        Wn, bn, out + E);

    edge_pred_csr<<<((long long)N * 32 + 255) / 256, 256>>>(
        rowptr, rowend, adj, eid, h1, h16, We, be, out, N);
}